// round 13
// baseline (speedup 1.0000x reference)
#include <cuda_runtime.h>
#include <cuda_fp16.h>
#include <cstdint>
#include <cstddef>

// ============================================================
// ExpanderLinear: y = x @ W^T + bias
// R12: A-fragments loaded DIRECTLY from gmem in fragment-major
// layout (no A smem, no A LDSM) -> smem crossbar no longer
// co-saturated with tensor pipe. B: 4-stage cp.async + ldmatrix.
// fp16 m16n8k16, 8 warps 64x32, 2 CTA/SM.
// ============================================================
#define INDIM   1024
#define OUTDIM  1024
#define MAXROWS 50048
#define BM 128
#define BN 128
#define BK 64
#define KTILES 16
#define THREADS 256
#define NSTAGE 4

#define ROWB 144                         // B smem row stride (LDSM conflict-free)
#define B_BYTES (BN * ROWB)              // 18432
#define STAGE_BYTES B_BYTES
#define SMEM_BYTES (NSTAGE * STAGE_BYTES) // 73728 (x2 CTAs = 147KB/SM)

#define NTILES_N (OUTDIM / BN)           // 8
#define WB_BLOCKS (NTILES_N * KTILES)    // 128 blocks of 18432 B

__device__ float  g_W[OUTDIM * INDIM];                              // fp32 scatter target
__device__ __align__(16) __half g_Wb[WB_BLOCKS * BN * (ROWB / 2)];  // fp16 padded B blocks
// fragment-major A: [mt 391][k16 64][m16 8][512B], lane l owns bytes l*16..+15
__device__ __align__(16) __half g_Xa[(size_t)MAXROWS * INDIM];
__device__ int    g_is64;

// ============================================================
// Helpers
// ============================================================
__device__ __forceinline__ uint32_t smem_u32(const void* p) {
    uint32_t a;
    asm("{ .reg .u64 t; cvta.to.shared.u64 t, %1; cvt.u32.u64 %0, t; }" : "=r"(a) : "l"(p));
    return a;
}
__device__ __forceinline__ void cp_async16(uint32_t dst, const void* src) {
    asm volatile("cp.async.cg.shared.global [%0], [%1], 16;" :: "r"(dst), "l"(src));
}
#define CP_COMMIT() asm volatile("cp.async.commit_group;" ::: "memory")
#define CP_WAIT0()  asm volatile("cp.async.wait_group 0;" ::: "memory")
#define CP_WAIT1()  asm volatile("cp.async.wait_group 1;" ::: "memory")
#define CP_WAIT2()  asm volatile("cp.async.wait_group 2;" ::: "memory")

__device__ __forceinline__ void ldsm4(uint32_t& r0, uint32_t& r1, uint32_t& r2,
                                      uint32_t& r3, uint32_t addr) {
    asm volatile("ldmatrix.sync.aligned.m8n8.x4.shared.b16 {%0,%1,%2,%3}, [%4];"
        : "=r"(r0), "=r"(r1), "=r"(r2), "=r"(r3) : "r"(addr));
}
__device__ __forceinline__ void mma_fp16(float* d, const uint32_t* a, const uint32_t* b) {
    asm volatile(
        "mma.sync.aligned.m16n8k16.row.col.f32.f16.f16.f32 "
        "{%0,%1,%2,%3}, {%4,%5,%6,%7}, {%8,%9}, {%0,%1,%2,%3};"
        : "+f"(d[0]), "+f"(d[1]), "+f"(d[2]), "+f"(d[3])
        : "r"(a[0]), "r"(a[1]), "r"(a[2]), "r"(a[3]), "r"(b[0]), "r"(b[1]));
}

// ============================================================
// 1) conv: x fp32 -> fragment-major fp16 g_Xa (zero-pad rows),
//    zero g_W (blocks 0..1023), detect dtype (block 0).
//    Block = one (mt, 64-k chunk): 128 rows x 64 k via smem transpose.
// ============================================================
__global__ void conv_kernel(const float* __restrict__ x, const int* __restrict__ ei,
                            int n_tok) {
    __shared__ __half sh[128 * 72];                  // stride 72 halfs (conflict-free)
    const int tid = threadIdx.x;
    const int mt  = blockIdx.x >> 4;
    const int kch = blockIdx.x & 15;                 // 64-k chunk

    // load 128 rows x 64 k (16 float4 per row), coalesced
    #pragma unroll
    for (int i = 0; i < 8; i++) {
        int idx = tid + i * 256;                     // 0..2047
        int row = idx >> 4, c4 = idx & 15;
        int grow = mt * 128 + row;
        __half2 h[2];
        if (grow < n_tok) {
            float4 v = *reinterpret_cast<const float4*>(
                x + (size_t)grow * INDIM + kch * 64 + c4 * 4);
            h[0] = __floats2half2_rn(v.x, v.y);
            h[1] = __floats2half2_rn(v.z, v.w);
        } else {
            h[0] = h[1] = __floats2half2_rn(0.f, 0.f);
        }
        *reinterpret_cast<uint2*>(&sh[row * 72 + c4 * 4]) = *reinterpret_cast<uint2*>(h);
    }
    __syncthreads();

    // emit 1024 16B chunks: ((mt*64 + kch*4 + k16l)*8 + m16)*512 + l*16
    #pragma unroll
    for (int i = 0; i < 4; i++) {
        int idx  = tid + i * 256;                    // 0..1023
        int sub  = idx >> 5;                         // 0..31
        int l    = idx & 31;
        int k16l = sub >> 3;                         // 0..3
        int m16  = sub & 7;                          // 0..7
        int g    = l >> 2, t = l & 3;
        int r0 = m16 * 16 + g;
        int k0 = k16l * 16 + 2 * t;
        uint4 v;
        v.x = *reinterpret_cast<const uint32_t*>(&sh[r0 * 72 + k0]);
        v.y = *reinterpret_cast<const uint32_t*>(&sh[(r0 + 8) * 72 + k0]);
        v.z = *reinterpret_cast<const uint32_t*>(&sh[r0 * 72 + k0 + 8]);
        v.w = *reinterpret_cast<const uint32_t*>(&sh[(r0 + 8) * 72 + k0 + 8]);
        size_t off = (((size_t)mt * 64 + kch * 4 + k16l) * 8 + m16) * 512 + l * 16;
        *reinterpret_cast<uint4*>(reinterpret_cast<char*>(g_Xa) + off) = v;
    }

    if (blockIdx.x < 1024) {
        int i = blockIdx.x * 256 + tid;
        reinterpret_cast<float4*>(g_W)[i] = make_float4(0.f, 0.f, 0.f, 0.f);
    }
    if (blockIdx.x == 0) {
        __shared__ int allzero;
        if (tid == 0) allzero = 1;
        __syncthreads();
        if (ei[tid * 2 + 1] != 0) allzero = 0;
        __syncthreads();
        if (tid == 0) g_is64 = allzero;
    }
}

// ============================================================
// 2) scatter (fp32 accumulate)
// ============================================================
__global__ void scatter_kernel(const int* __restrict__ ei,
                               const float* __restrict__ val, int nnz) {
    int i = blockIdx.x * 256 + threadIdx.x;
    if (i >= nnz) return;
    int r, c;
    if (g_is64) {
        const long long* e = (const long long*)ei;
        r = (int)e[i];
        c = (int)e[nnz + i];
    } else {
        r = ei[i];
        c = ei[nnz + i];
    }
    atomicAdd(&g_W[r * INDIM + c], val[i]);
}

// ============================================================
// 3) reblock: W fp32 -> fp16 blocks [nt][kc], 128 rows x 144B
// ============================================================
__global__ void reblock_kernel() {
    int i = blockIdx.x * 256 + threadIdx.x;          // 0..131071
    int blk    = i >> 10;                            // 0..127 = nt*16 + kc
    int within = i & 1023;
    int r  = within >> 3;
    int c  = within & 7;
    int nt = blk >> 4;
    int kc = blk & 15;
    const float4* src = reinterpret_cast<const float4*>(
        &g_W[(size_t)(nt * 128 + r) * INDIM + kc * 64 + c * 8]);
    float4 v0 = src[0], v1 = src[1];
    __half2 h[4];
    h[0] = __floats2half2_rn(v0.x, v0.y);
    h[1] = __floats2half2_rn(v0.z, v0.w);
    h[2] = __floats2half2_rn(v1.x, v1.y);
    h[3] = __floats2half2_rn(v1.z, v1.w);
    *reinterpret_cast<uint4*>(reinterpret_cast<char*>(g_Wb)
        + (size_t)blk * B_BYTES + r * ROWB + c * 16) = *reinterpret_cast<uint4*>(h);
}

// ============================================================
// 4) GEMM: out[m,n] = sum_k X[m,k]*W[n,k] + bias[n]
// ============================================================
__global__ void __launch_bounds__(THREADS, 2)
gemm_kernel(const float* __restrict__ bias, float* __restrict__ out, int n_tok) {
    extern __shared__ char smem[];
    uint32_t sbase = smem_u32(smem);

    const int tid  = threadIdx.x;
    const int wid  = tid >> 5;
    const int lane = tid & 31;
    const int g    = lane >> 2;
    const int t    = lane & 3;

    const int n0 = (blockIdx.x & 7) * BN;   // n fastest -> A reuse in L1/L2
    const int m0 = (blockIdx.x >> 3) * BM;
    const int nt = n0 >> 7;
    const int mt = m0 >> 7;

    const int wm = (wid & 1) * 64;
    const int wn = (wid >> 1) * 32;

    // A fragment-major base for this warp/lane
    const char* abase = reinterpret_cast<const char*>(g_Xa)
                        + (size_t)mt * 262144 + (wm >> 4) * 512 + lane * 16;

    // B ldmatrix per-lane offset within a stage
    const uint32_t b_lane = (uint32_t)(wn + (lane >> 4) * 8 + (lane & 7)) * ROWB
                            + ((lane >> 3) & 1) * 16;

    // ---- B stage loader: 1152 chunks of 16B ----
    auto load_stage = [&](uint32_t dst, int kc) {
        const char* bsrc = reinterpret_cast<const char*>(g_Wb)
                           + ((size_t)nt * KTILES + kc) * B_BYTES;
        #pragma unroll
        for (int it = 0; it < 5; it++) {
            int ch = tid + it * THREADS;
            if (ch < 1152) cp_async16(dst + ch * 16, bsrc + ch * 16);
        }
        CP_COMMIT();
    };

    float acc[4][4][4];
    #pragma unroll
    for (int i = 0; i < 4; i++)
        #pragma unroll
        for (int j = 0; j < 4; j++)
            #pragma unroll
            for (int r = 0; r < 4; r++) acc[i][j][r] = 0.f;

    uint32_t afrag[2][4][4];
    uint32_t bfrag[2][4][2];

    // A fragment loader: 4 LDG.128 for one k16 slice
    auto loadA = [&](int k16, int fb) {
        #pragma unroll
        for (int tm = 0; tm < 4; tm++) {
            uint4 v = *reinterpret_cast<const uint4*>(abase + k16 * 4096 + tm * 512);
            afrag[fb][tm][0] = v.x; afrag[fb][tm][1] = v.y;
            afrag[fb][tm][2] = v.z; afrag[fb][tm][3] = v.w;
        }
    };

    uint32_t st0 = sbase, st1 = sbase + STAGE_BYTES,
             st2 = sbase + 2 * STAGE_BYTES, st3 = sbase + 3 * STAGE_BYTES;

    load_stage(st0, 0);
    load_stage(st1, 1);
    load_stage(st2, 2);
    loadA(0, 0);

    for (int kc = 0; kc < KTILES; kc++) {
        if (kc <= 13) { CP_WAIT2(); } else if (kc == 14) { CP_WAIT1(); } else { CP_WAIT0(); }
        __syncthreads();                      // stage st0 (kc) ready
        if (kc + 3 < KTILES) load_stage(st3, kc + 3);

        const uint32_t baddr = st0 + b_lane;

        auto loadB = [&](int ks, int fb) {
            #pragma unroll
            for (int tnp = 0; tnp < 2; tnp++) {
                uint32_t r0, r1, r2, r3;
                ldsm4(r0, r1, r2, r3, baddr + tnp * (16 * ROWB) + ks * 32);
                bfrag[fb][2 * tnp][0]     = r0;
                bfrag[fb][2 * tnp][1]     = r1;
                bfrag[fb][2 * tnp + 1][0] = r2;
                bfrag[fb][2 * tnp + 1][1] = r3;
            }
        };

        loadB(0, 0);
        #pragma unroll
        for (int ks = 0; ks < 4; ks++) {
            const int cur = ks & 1;
            const int k16 = kc * 4 + ks;
            if (ks < 3) loadB(ks + 1, cur ^ 1);
            if (k16 + 1 < 64) loadA(k16 + 1, cur ^ 1);   // gmem, stage-independent
            #pragma unroll
            for (int tm = 0; tm < 4; tm++)
                #pragma unroll
                for (int tn = 0; tn < 4; tn++)
                    mma_fp16(acc[tm][tn], afrag[cur][tm], bfrag[cur][tn]);
        }

        uint32_t tmp = st0; st0 = st1; st1 = st2; st2 = st3; st3 = tmp;
    }

    // ---- epilogue: add bias, store ----
    #pragma unroll
    for (int tn = 0; tn < 4; tn++) {
        const int c = n0 + wn + tn * 8 + 2 * t;
        const float bv0 = bias[c];
        const float bv1 = bias[c + 1];
        #pragma unroll
        for (int tm = 0; tm < 4; tm++) {
            const int r0 = m0 + wm + tm * 16 + g;
            const int r1 = r0 + 8;
            if (r0 < n_tok) {
                float2 v = make_float2(acc[tm][tn][0] + bv0, acc[tm][tn][1] + bv1);
                *reinterpret_cast<float2*>(&out[(size_t)r0 * OUTDIM + c]) = v;
            }
            if (r1 < n_tok) {
                float2 v = make_float2(acc[tm][tn][2] + bv0, acc[tm][tn][3] + bv1);
                *reinterpret_cast<float2*>(&out[(size_t)r1 * OUTDIM + c]) = v;
            }
        }
    }
}

// ============================================================
// Launch: 4 kernels (conv, scatter, reblock, gemm) -> gemm is #4
// ============================================================
extern "C" void kernel_launch(void* const* d_in, const int* in_sizes, int n_in,
                              void* d_out, int out_size) {
    const float* x    = (const float*)d_in[0];
    const float* wval = (const float*)d_in[1];
    const float* bias = (const float*)d_in[2];
    const int*   ei   = (const int*)d_in[3];

    int n_tok = in_sizes[0] / INDIM;           // 50000
    int nnz   = in_sizes[1];                   // 65536
    float* out = (float*)d_out;

    int mtiles = (n_tok + BM - 1) / BM;        // 391
    conv_kernel<<<mtiles * 16, 256>>>(x, ei, n_tok);
    scatter_kernel<<<(nnz + 255) / 256, 256>>>(ei, wval, nnz);
    reblock_kernel<<<(WB_BLOCKS * 1024) / 256, 256>>>();

    cudaFuncSetAttribute(gemm_kernel, cudaFuncAttributeMaxDynamicSharedMemorySize, SMEM_BYTES);
    gemm_kernel<<<mtiles * (OUTDIM / BN), THREADS, SMEM_BYTES>>>(bias, out, n_tok);
}

// round 14
// speedup vs baseline: 1.0320x; 1.0320x over previous
#include <cuda_runtime.h>
#include <cuda_fp16.h>
#include <cstdint>
#include <cstddef>

// ============================================================
// ExpanderLinear: y = x @ W^T + bias
// R13 = R11 (best: 322us, gemm 271us) + warp-staggered ks order:
// each warp rotates its k16-group schedule by (wid&3) so the
// post-barrier LDSM bursts of the 16 warps/SM de-correlate.
// fp16 m16n8k16, BK=64, 3-stage cp.async, 8 warps 64x32, 2 CTA/SM.
// ============================================================
#define INDIM   1024
#define OUTDIM  1024
#define MAXROWS 50048
#define BM 128
#define BN 128
#define BK 64
#define KTILES 16
#define THREADS 256
#define NSTAGE 3

#define ROWB 144                         // 128B data + 16B pad (LDSM conflict-free)
#define A_BYTES (BM * ROWB)              // 18432
#define B_BYTES (BN * ROWB)              // 18432
#define STAGE_BYTES (A_BYTES + B_BYTES)  // 36864
#define SMEM_BYTES (NSTAGE * STAGE_BYTES) // 110592 (x2 CTAs = 221KB/SM)

#define NTILES_N (OUTDIM / BN)           // 8
#define WB_BLOCKS (NTILES_N * KTILES)    // 128 blocks of 18432 B

__device__ float  g_W[OUTDIM * INDIM];                              // fp32 scatter target
__device__ __align__(16) __half g_Wb[WB_BLOCKS * BN * (ROWB / 2)];  // fp16 padded blocks
__device__ __align__(16) __half g_Xh[(size_t)MAXROWS * INDIM];      // fp16 x, zero-padded
__device__ int    g_is64;

// ============================================================
// Helpers
// ============================================================
__device__ __forceinline__ uint32_t smem_u32(const void* p) {
    uint32_t a;
    asm("{ .reg .u64 t; cvta.to.shared.u64 t, %1; cvt.u32.u64 %0, t; }" : "=r"(a) : "l"(p));
    return a;
}
__device__ __forceinline__ void cp_async16(uint32_t dst, const void* src) {
    asm volatile("cp.async.cg.shared.global [%0], [%1], 16;" :: "r"(dst), "l"(src));
}
#define CP_COMMIT() asm volatile("cp.async.commit_group;" ::: "memory")
#define CP_WAIT0()  asm volatile("cp.async.wait_group 0;" ::: "memory")
#define CP_WAIT1()  asm volatile("cp.async.wait_group 1;" ::: "memory")

__device__ __forceinline__ void ldsm4(uint32_t& r0, uint32_t& r1, uint32_t& r2,
                                      uint32_t& r3, uint32_t addr) {
    asm volatile("ldmatrix.sync.aligned.m8n8.x4.shared.b16 {%0,%1,%2,%3}, [%4];"
        : "=r"(r0), "=r"(r1), "=r"(r2), "=r"(r3) : "r"(addr));
}
__device__ __forceinline__ void mma_fp16(float* d, const uint32_t* a, const uint32_t* b) {
    asm volatile(
        "mma.sync.aligned.m16n8k16.row.col.f32.f16.f16.f32 "
        "{%0,%1,%2,%3}, {%4,%5,%6,%7}, {%8,%9}, {%0,%1,%2,%3};"
        : "+f"(d[0]), "+f"(d[1]), "+f"(d[2]), "+f"(d[3])
        : "r"(a[0]), "r"(a[1]), "r"(a[2]), "r"(a[3]), "r"(b[0]), "r"(b[1]));
}

// ============================================================
// 1) conv: x fp32 -> fp16 (zero-pad rows), zero g_W, detect dtype
// ============================================================
__global__ void conv_kernel(const float* __restrict__ x, const int* __restrict__ ei,
                            int n_tok) {
    int i = blockIdx.x * 256 + threadIdx.x;          // chunk: 8 halfs
    int row = i >> 7;
    int c   = i & 127;
    __half2 h[4];
    if (row < n_tok) {
        const float4* src = reinterpret_cast<const float4*>(x + (size_t)row * INDIM + c * 8);
        float4 v0 = src[0], v1 = src[1];
        h[0] = __floats2half2_rn(v0.x, v0.y);
        h[1] = __floats2half2_rn(v0.z, v0.w);
        h[2] = __floats2half2_rn(v1.x, v1.y);
        h[3] = __floats2half2_rn(v1.z, v1.w);
    } else {
        h[0] = h[1] = h[2] = h[3] = __floats2half2_rn(0.f, 0.f);
    }
    *reinterpret_cast<uint4*>(g_Xh + (size_t)i * 8) = *reinterpret_cast<uint4*>(h);

    if (i < OUTDIM * INDIM / 4)
        reinterpret_cast<float4*>(g_W)[i] = make_float4(0.f, 0.f, 0.f, 0.f);

    if (blockIdx.x == 0) {
        __shared__ int allzero;
        if (threadIdx.x == 0) allzero = 1;
        __syncthreads();
        if (ei[threadIdx.x * 2 + 1] != 0) allzero = 0;
        __syncthreads();
        if (threadIdx.x == 0) g_is64 = allzero;
    }
}

// ============================================================
// 2) scatter (fp32 accumulate; fp16 RN happens in reblock)
// ============================================================
__global__ void scatter_kernel(const int* __restrict__ ei,
                               const float* __restrict__ val, int nnz) {
    int i = blockIdx.x * 256 + threadIdx.x;
    if (i >= nnz) return;
    int r, c;
    if (g_is64) {
        const long long* e = (const long long*)ei;
        r = (int)e[i];
        c = (int)e[nnz + i];
    } else {
        r = ei[i];
        c = ei[nnz + i];
    }
    atomicAdd(&g_W[r * INDIM + c], val[i]);
}

// ============================================================
// 3) reblock: W fp32 -> fp16 blocks [nt][kc], 128 rows x 144B
// ============================================================
__global__ void reblock_kernel() {
    int i = blockIdx.x * 256 + threadIdx.x;          // 0..131071
    int blk    = i >> 10;                            // 0..127 = nt*16 + kc
    int within = i & 1023;
    int r  = within >> 3;
    int c  = within & 7;
    int nt = blk >> 4;
    int kc = blk & 15;
    const float4* src = reinterpret_cast<const float4*>(
        &g_W[(size_t)(nt * 128 + r) * INDIM + kc * 64 + c * 8]);
    float4 v0 = src[0], v1 = src[1];
    __half2 h[4];
    h[0] = __floats2half2_rn(v0.x, v0.y);
    h[1] = __floats2half2_rn(v0.z, v0.w);
    h[2] = __floats2half2_rn(v1.x, v1.y);
    h[3] = __floats2half2_rn(v1.z, v1.w);
    *reinterpret_cast<uint4*>(reinterpret_cast<char*>(g_Wb)
        + (size_t)blk * B_BYTES + r * ROWB + c * 16) = *reinterpret_cast<uint4*>(h);
}

// ============================================================
// 4) GEMM: out[m,n] = sum_k X[m,k]*W[n,k] + bias[n]
// ============================================================
__global__ void __launch_bounds__(THREADS, 2)
gemm_kernel(const float* __restrict__ bias, float* __restrict__ out, int n_tok) {
    extern __shared__ char smem[];
    uint32_t sbase = smem_u32(smem);

    const int tid  = threadIdx.x;
    const int wid  = tid >> 5;
    const int lane = tid & 31;
    const int g    = lane >> 2;
    const int t    = lane & 3;
    const int kofs = wid & 3;               // per-warp ks rotation

    const int n0 = (blockIdx.x & 7) * BN;   // n fastest -> A-tile L2 reuse
    const int m0 = (blockIdx.x >> 3) * BM;
    const int nt = n0 >> 7;

    const int wm = (wid & 1) * 64;
    const int wn = (wid >> 1) * 32;

    // ldmatrix per-lane offsets (within a stage)
    const uint32_t a_lane = (uint32_t)(wm + (lane & 15)) * ROWB + (lane >> 4) * 16;
    const uint32_t b_lane = (uint32_t)(wn + (lane >> 4) * 8 + (lane & 7)) * ROWB
                            + ((lane >> 3) & 1) * 16 + A_BYTES;

    // ---- stage loader: A 1024 chunks + B 1152 chunks of 16B ----
    auto load_stage = [&](uint32_t dst, int kc) {
        #pragma unroll
        for (int it = 0; it < 4; it++) {
            int ch = tid + it * THREADS;
            int r = ch >> 3, c = ch & 7;
            cp_async16(dst + r * ROWB + c * 16,
                       g_Xh + (size_t)(m0 + r) * INDIM + kc * 64 + c * 8);
        }
        const char* bsrc = reinterpret_cast<const char*>(g_Wb)
                           + ((size_t)nt * KTILES + kc) * B_BYTES;
        uint32_t dstB = dst + A_BYTES;
        #pragma unroll
        for (int it = 0; it < 5; it++) {
            int ch = tid + it * THREADS;
            if (ch < 1152) cp_async16(dstB + ch * 16, bsrc + ch * 16);
        }
        CP_COMMIT();
    };

    float acc[4][4][4];
    #pragma unroll
    for (int i = 0; i < 4; i++)
        #pragma unroll
        for (int j = 0; j < 4; j++)
            #pragma unroll
            for (int r = 0; r < 4; r++) acc[i][j][r] = 0.f;

    uint32_t afrag[2][4][4];
    uint32_t bfrag[2][4][2];

    uint32_t st0 = sbase;                     // stage holding kc
    uint32_t st1 = sbase + STAGE_BYTES;       // kc+1
    uint32_t st2 = sbase + 2 * STAGE_BYTES;   // kc+2 (being filled)

    load_stage(st0, 0);
    load_stage(st1, 1);

    for (int kc = 0; kc < KTILES; kc++) {
        if (kc + 1 < KTILES) { CP_WAIT1(); } else { CP_WAIT0(); }
        __syncthreads();                      // stage st0 (kc) ready for all warps
        if (kc + 2 < KTILES) load_stage(st2, kc + 2);

        const uint32_t aaddr = st0 + a_lane;
        const uint32_t baddr = st0 + b_lane;

        // fragment loader for one k16 slice (physical index ksp) into buffer fb
        auto load_frag = [&](int ksp, int fb) {
            #pragma unroll
            for (int tm = 0; tm < 4; tm++)
                ldsm4(afrag[fb][tm][0], afrag[fb][tm][1],
                      afrag[fb][tm][2], afrag[fb][tm][3],
                      aaddr + tm * (16 * ROWB) + ksp * 32);
            #pragma unroll
            for (int tnp = 0; tnp < 2; tnp++) {
                uint32_t r0, r1, r2, r3;
                ldsm4(r0, r1, r2, r3, baddr + tnp * (16 * ROWB) + ksp * 32);
                bfrag[fb][2 * tnp][0]     = r0;
                bfrag[fb][2 * tnp][1]     = r1;
                bfrag[fb][2 * tnp + 1][0] = r2;
                bfrag[fb][2 * tnp + 1][1] = r3;
            }
        };

        // warp-staggered ks order: warp wid starts at group kofs
        load_frag(kofs, 0);
        #pragma unroll
        for (int ks = 0; ks < 4; ks++) {
            const int cur = ks & 1;
            if (ks < 3) load_frag((ks + 1 + kofs) & 3, cur ^ 1);  // hide LDSM under MMAs
            #pragma unroll
            for (int tm = 0; tm < 4; tm++)
                #pragma unroll
                for (int tn = 0; tn < 4; tn++)
                    mma_fp16(acc[tm][tn], afrag[cur][tm], bfrag[cur][tn]);
        }

        // rotate stage bases (3 registers, no modulo)
        uint32_t tmp = st0; st0 = st1; st1 = st2; st2 = tmp;
    }

    // ---- epilogue: add bias, store (float2 per row-piece) ----
    #pragma unroll
    for (int tn = 0; tn < 4; tn++) {
        const int c = n0 + wn + tn * 8 + 2 * t;
        const float bv0 = bias[c];
        const float bv1 = bias[c + 1];
        #pragma unroll
        for (int tm = 0; tm < 4; tm++) {
            const int r0 = m0 + wm + tm * 16 + g;
            const int r1 = r0 + 8;
            if (r0 < n_tok) {
                float2 v = make_float2(acc[tm][tn][0] + bv0, acc[tm][tn][1] + bv1);
                *reinterpret_cast<float2*>(&out[(size_t)r0 * OUTDIM + c]) = v;
            }
            if (r1 < n_tok) {
                float2 v = make_float2(acc[tm][tn][2] + bv0, acc[tm][tn][3] + bv1);
                *reinterpret_cast<float2*>(&out[(size_t)r1 * OUTDIM + c]) = v;
            }
        }
    }
}

// ============================================================
// Launch: 4 kernels (conv, scatter, reblock, gemm) -> gemm is #4
// ============================================================
extern "C" void kernel_launch(void* const* d_in, const int* in_sizes, int n_in,
                              void* d_out, int out_size) {
    const float* x    = (const float*)d_in[0];
    const float* wval = (const float*)d_in[1];
    const float* bias = (const float*)d_in[2];
    const int*   ei   = (const int*)d_in[3];

    int n_tok = in_sizes[0] / INDIM;           // 50000
    int nnz   = in_sizes[1];                   // 65536
    float* out = (float*)d_out;

    conv_kernel<<<(MAXROWS * (INDIM / 8)) / 256, 256>>>(x, ei, n_tok);
    scatter_kernel<<<(nnz + 255) / 256, 256>>>(ei, wval, nnz);
    reblock_kernel<<<(WB_BLOCKS * 1024) / 256, 256>>>();

    int mtiles = (n_tok + BM - 1) / BM;        // 391
    cudaFuncSetAttribute(gemm_kernel, cudaFuncAttributeMaxDynamicSharedMemorySize, SMEM_BYTES);
    gemm_kernel<<<mtiles * (OUTDIM / BN), THREADS, SMEM_BYTES>>>(bias, out, n_tok);
}

// round 15
// speedup vs baseline: 1.0325x; 1.0005x over previous
#include <cuda_runtime.h>
#include <cuda_fp16.h>
#include <cstdint>
#include <cstddef>

// ============================================================
// ExpanderLinear: y = x @ W^T + bias
// R14 = R11 + CUTLASS-style rotated mainloop: wait+barrier moved to
// ks2, next-stage ks0 fragment prefetched at ks3 -> no LDSM on the
// post-barrier critical path. fp16 m16n8k16, BK=64, 3-stage
// cp.async, 8 warps 64x32, 2 CTA/SM.
// ============================================================
#define INDIM   1024
#define OUTDIM  1024
#define MAXROWS 50048
#define BM 128
#define BN 128
#define BK 64
#define KTILES 16
#define THREADS 256
#define NSTAGE 3

#define ROWB 144                         // 128B data + 16B pad (LDSM conflict-free)
#define A_BYTES (BM * ROWB)              // 18432
#define B_BYTES (BN * ROWB)              // 18432
#define STAGE_BYTES (A_BYTES + B_BYTES)  // 36864
#define SMEM_BYTES (NSTAGE * STAGE_BYTES) // 110592 (x2 CTAs = 221KB/SM)

#define NTILES_N (OUTDIM / BN)           // 8
#define WB_BLOCKS (NTILES_N * KTILES)    // 128 blocks of 18432 B

__device__ float  g_W[OUTDIM * INDIM];                              // fp32 scatter target
__device__ __align__(16) __half g_Wb[WB_BLOCKS * BN * (ROWB / 2)];  // fp16 padded blocks
__device__ __align__(16) __half g_Xh[(size_t)MAXROWS * INDIM];      // fp16 x, zero-padded
__device__ int    g_is64;

// ============================================================
// Helpers
// ============================================================
__device__ __forceinline__ uint32_t smem_u32(const void* p) {
    uint32_t a;
    asm("{ .reg .u64 t; cvta.to.shared.u64 t, %1; cvt.u32.u64 %0, t; }" : "=r"(a) : "l"(p));
    return a;
}
__device__ __forceinline__ void cp_async16(uint32_t dst, const void* src) {
    asm volatile("cp.async.cg.shared.global [%0], [%1], 16;" :: "r"(dst), "l"(src));
}
#define CP_COMMIT() asm volatile("cp.async.commit_group;" ::: "memory")
#define CP_WAIT0()  asm volatile("cp.async.wait_group 0;" ::: "memory")
#define CP_WAIT1()  asm volatile("cp.async.wait_group 1;" ::: "memory")

__device__ __forceinline__ void ldsm4(uint32_t& r0, uint32_t& r1, uint32_t& r2,
                                      uint32_t& r3, uint32_t addr) {
    asm volatile("ldmatrix.sync.aligned.m8n8.x4.shared.b16 {%0,%1,%2,%3}, [%4];"
        : "=r"(r0), "=r"(r1), "=r"(r2), "=r"(r3) : "r"(addr));
}
__device__ __forceinline__ void mma_fp16(float* d, const uint32_t* a, const uint32_t* b) {
    asm volatile(
        "mma.sync.aligned.m16n8k16.row.col.f32.f16.f16.f32 "
        "{%0,%1,%2,%3}, {%4,%5,%6,%7}, {%8,%9}, {%0,%1,%2,%3};"
        : "+f"(d[0]), "+f"(d[1]), "+f"(d[2]), "+f"(d[3])
        : "r"(a[0]), "r"(a[1]), "r"(a[2]), "r"(a[3]), "r"(b[0]), "r"(b[1]));
}

// ============================================================
// 1) conv: x fp32 -> fp16 (zero-pad rows), zero g_W, detect dtype
// ============================================================
__global__ void conv_kernel(const float* __restrict__ x, const int* __restrict__ ei,
                            int n_tok) {
    int i = blockIdx.x * 256 + threadIdx.x;          // chunk: 8 halfs
    int row = i >> 7;
    int c   = i & 127;
    __half2 h[4];
    if (row < n_tok) {
        const float4* src = reinterpret_cast<const float4*>(x + (size_t)row * INDIM + c * 8);
        float4 v0 = src[0], v1 = src[1];
        h[0] = __floats2half2_rn(v0.x, v0.y);
        h[1] = __floats2half2_rn(v0.z, v0.w);
        h[2] = __floats2half2_rn(v1.x, v1.y);
        h[3] = __floats2half2_rn(v1.z, v1.w);
    } else {
        h[0] = h[1] = h[2] = h[3] = __floats2half2_rn(0.f, 0.f);
    }
    *reinterpret_cast<uint4*>(g_Xh + (size_t)i * 8) = *reinterpret_cast<uint4*>(h);

    if (i < OUTDIM * INDIM / 4)
        reinterpret_cast<float4*>(g_W)[i] = make_float4(0.f, 0.f, 0.f, 0.f);

    if (blockIdx.x == 0) {
        __shared__ int allzero;
        if (threadIdx.x == 0) allzero = 1;
        __syncthreads();
        if (ei[threadIdx.x * 2 + 1] != 0) allzero = 0;
        __syncthreads();
        if (threadIdx.x == 0) g_is64 = allzero;
    }
}

// ============================================================
// 2) scatter (fp32 accumulate; fp16 RN happens in reblock)
// ============================================================
__global__ void scatter_kernel(const int* __restrict__ ei,
                               const float* __restrict__ val, int nnz) {
    int i = blockIdx.x * 256 + threadIdx.x;
    if (i >= nnz) return;
    int r, c;
    if (g_is64) {
        const long long* e = (const long long*)ei;
        r = (int)e[i];
        c = (int)e[nnz + i];
    } else {
        r = ei[i];
        c = ei[nnz + i];
    }
    atomicAdd(&g_W[r * INDIM + c], val[i]);
}

// ============================================================
// 3) reblock: W fp32 -> fp16 blocks [nt][kc], 128 rows x 144B
// ============================================================
__global__ void reblock_kernel() {
    int i = blockIdx.x * 256 + threadIdx.x;          // 0..131071
    int blk    = i >> 10;                            // 0..127 = nt*16 + kc
    int within = i & 1023;
    int r  = within >> 3;
    int c  = within & 7;
    int nt = blk >> 4;
    int kc = blk & 15;
    const float4* src = reinterpret_cast<const float4*>(
        &g_W[(size_t)(nt * 128 + r) * INDIM + kc * 64 + c * 8]);
    float4 v0 = src[0], v1 = src[1];
    __half2 h[4];
    h[0] = __floats2half2_rn(v0.x, v0.y);
    h[1] = __floats2half2_rn(v0.z, v0.w);
    h[2] = __floats2half2_rn(v1.x, v1.y);
    h[3] = __floats2half2_rn(v1.z, v1.w);
    *reinterpret_cast<uint4*>(reinterpret_cast<char*>(g_Wb)
        + (size_t)blk * B_BYTES + r * ROWB + c * 16) = *reinterpret_cast<uint4*>(h);
}

// ============================================================
// 4) GEMM: out[m,n] = sum_k X[m,k]*W[n,k] + bias[n]
// ============================================================
__global__ void __launch_bounds__(THREADS, 2)
gemm_kernel(const float* __restrict__ bias, float* __restrict__ out, int n_tok) {
    extern __shared__ char smem[];
    uint32_t sbase = smem_u32(smem);

    const int tid  = threadIdx.x;
    const int wid  = tid >> 5;
    const int lane = tid & 31;
    const int g    = lane >> 2;
    const int t    = lane & 3;

    const int n0 = (blockIdx.x & 7) * BN;   // n fastest -> A-tile L2 reuse
    const int m0 = (blockIdx.x >> 3) * BM;
    const int nt = n0 >> 7;

    const int wm = (wid & 1) * 64;
    const int wn = (wid >> 1) * 32;

    // ldmatrix per-lane offsets (within a stage)
    const uint32_t a_lane = (uint32_t)(wm + (lane & 15)) * ROWB + (lane >> 4) * 16;
    const uint32_t b_lane = (uint32_t)(wn + (lane >> 4) * 8 + (lane & 7)) * ROWB
                            + ((lane >> 3) & 1) * 16 + A_BYTES;

    // ---- stage loader: A 1024 chunks + B 1152 chunks of 16B ----
    auto load_stage = [&](uint32_t dst, int kc) {
        #pragma unroll
        for (int it = 0; it < 4; it++) {
            int ch = tid + it * THREADS;
            int r = ch >> 3, c = ch & 7;
            cp_async16(dst + r * ROWB + c * 16,
                       g_Xh + (size_t)(m0 + r) * INDIM + kc * 64 + c * 8);
        }
        const char* bsrc = reinterpret_cast<const char*>(g_Wb)
                           + ((size_t)nt * KTILES + kc) * B_BYTES;
        uint32_t dstB = dst + A_BYTES;
        #pragma unroll
        for (int it = 0; it < 5; it++) {
            int ch = tid + it * THREADS;
            if (ch < 1152) cp_async16(dstB + ch * 16, bsrc + ch * 16);
        }
        CP_COMMIT();
    };

    float acc[4][4][4];
    #pragma unroll
    for (int i = 0; i < 4; i++)
        #pragma unroll
        for (int j = 0; j < 4; j++)
            #pragma unroll
            for (int r = 0; r < 4; r++) acc[i][j][r] = 0.f;

    uint32_t afrag[2][4][4];
    uint32_t bfrag[2][4][2];

    uint32_t st0 = sbase;                     // stage holding kc
    uint32_t st1 = sbase + STAGE_BYTES;       // kc+1
    uint32_t st2 = sbase + 2 * STAGE_BYTES;   // free / being filled with kc+2

    // fragment loader from stage base stg, k16 slice ksp, buffer fb
    auto load_frag = [&](uint32_t stg, int ksp, int fb) {
        const uint32_t aaddr = stg + a_lane;
        const uint32_t baddr = stg + b_lane;
        #pragma unroll
        for (int tm = 0; tm < 4; tm++)
            ldsm4(afrag[fb][tm][0], afrag[fb][tm][1],
                  afrag[fb][tm][2], afrag[fb][tm][3],
                  aaddr + tm * (16 * ROWB) + ksp * 32);
        #pragma unroll
        for (int tnp = 0; tnp < 2; tnp++) {
            uint32_t r0, r1, r2, r3;
            ldsm4(r0, r1, r2, r3, baddr + tnp * (16 * ROWB) + ksp * 32);
            bfrag[fb][2 * tnp][0]     = r0;
            bfrag[fb][2 * tnp][1]     = r1;
            bfrag[fb][2 * tnp + 1][0] = r2;
            bfrag[fb][2 * tnp + 1][1] = r3;
        }
    };

    auto mma_all = [&](int fb) {
        #pragma unroll
        for (int tm = 0; tm < 4; tm++)
            #pragma unroll
            for (int tn = 0; tn < 4; tn++)
                mma_fp16(acc[tm][tn], afrag[fb][tm], bfrag[fb][tn]);
    };

    // prologue: G0 (stage0), G1 (stage1); wait G0; first fragments
    load_stage(st0, 0);
    load_stage(st1, 1);
    CP_WAIT1();
    __syncthreads();
    load_frag(st0, 0, 0);

    for (int kc = 0; kc < KTILES; kc++) {
        // ks0
        load_frag(st0, 1, 1);
        mma_all(0);
        // ks1
        load_frag(st0, 2, 0);
        mma_all(1);
        // ks2: retire the next stage's group + barrier, mma under it
        load_frag(st0, 3, 1);
        mma_all(0);
        if (kc + 1 < KTILES) { CP_WAIT0(); }      // outstanding: {G_{kc+1}} only
        __syncthreads();                          // stage kc+1 visible to all
        // ks3: prefetch next stage's ks0, refill free stage, mma
        if (kc + 1 < KTILES) load_frag(st1, 0, 0);
        if (kc + 2 < KTILES) load_stage(st2, kc + 2);
        mma_all(1);

        // rotate stage bases (3 registers, no modulo)
        uint32_t tmp = st0; st0 = st1; st1 = st2; st2 = tmp;
    }

    // ---- epilogue: add bias, store (float2 per row-piece) ----
    #pragma unroll
    for (int tn = 0; tn < 4; tn++) {
        const int c = n0 + wn + tn * 8 + 2 * t;
        const float bv0 = bias[c];
        const float bv1 = bias[c + 1];
        #pragma unroll
        for (int tm = 0; tm < 4; tm++) {
            const int r0 = m0 + wm + tm * 16 + g;
            const int r1 = r0 + 8;
            if (r0 < n_tok) {
                float2 v = make_float2(acc[tm][tn][0] + bv0, acc[tm][tn][1] + bv1);
                *reinterpret_cast<float2*>(&out[(size_t)r0 * OUTDIM + c]) = v;
            }
            if (r1 < n_tok) {
                float2 v = make_float2(acc[tm][tn][2] + bv0, acc[tm][tn][3] + bv1);
                *reinterpret_cast<float2*>(&out[(size_t)r1 * OUTDIM + c]) = v;
            }
        }
    }
}

// ============================================================
// Launch: 4 kernels (conv, scatter, reblock, gemm) -> gemm is #4
// ============================================================
extern "C" void kernel_launch(void* const* d_in, const int* in_sizes, int n_in,
                              void* d_out, int out_size) {
    const float* x    = (const float*)d_in[0];
    const float* wval = (const float*)d_in[1];
    const float* bias = (const float*)d_in[2];
    const int*   ei   = (const int*)d_in[3];

    int n_tok = in_sizes[0] / INDIM;           // 50000
    int nnz   = in_sizes[1];                   // 65536
    float* out = (float*)d_out;

    conv_kernel<<<(MAXROWS * (INDIM / 8)) / 256, 256>>>(x, ei, n_tok);
    scatter_kernel<<<(nnz + 255) / 256, 256>>>(ei, wval, nnz);
    reblock_kernel<<<(WB_BLOCKS * 1024) / 256, 256>>>();

    int mtiles = (n_tok + BM - 1) / BM;        // 391
    cudaFuncSetAttribute(gemm_kernel, cudaFuncAttributeMaxDynamicSharedMemorySize, SMEM_BYTES);
    gemm_kernel<<<mtiles * (OUTDIM / BN), THREADS, SMEM_BYTES>>>(bias, out, n_tok);
}

// round 16
// speedup vs baseline: 1.0837x; 1.0496x over previous
#include <cuda_runtime.h>
#include <cuda_fp16.h>
#include <cstdint>
#include <cstddef>

// ============================================================
// ExpanderLinear: y = x @ W^T + bias
// R15 = R11 gemm (best: gemm 271us) + leaner prep:
//  - scatter atomicAdd(__half) DIRECTLY into padded fp16 g_Wb
//    (reblock kernel and dense fp32 g_W deleted)
//  - conv split into 2 half-row kernels (gemm stays launch #4),
//    zeroing g_Wb (2.25MB) along the way
// fp16 m16n8k16, BK=64, 3-stage cp.async, 8 warps 64x32, 2 CTA/SM.
// ============================================================
#define INDIM   1024
#define OUTDIM  1024
#define MAXROWS 50048
#define HALFROWS (MAXROWS / 2)           // 25024
#define BM 128
#define BN 128
#define BK 64
#define KTILES 16
#define THREADS 256
#define NSTAGE 3

#define ROWB 144                         // 128B data + 16B pad (LDSM conflict-free)
#define A_BYTES (BM * ROWB)              // 18432
#define B_BYTES (BN * ROWB)              // 18432
#define STAGE_BYTES (A_BYTES + B_BYTES)  // 36864
#define SMEM_BYTES (NSTAGE * STAGE_BYTES) // 110592 (x2 CTAs = 221KB/SM)

#define NTILES_N (OUTDIM / BN)           // 8
#define WB_BLOCKS (NTILES_N * KTILES)    // 128 blocks of 18432 B
#define WB_HALFS (WB_BLOCKS * BN * (ROWB / 2))   // 1179648
#define WB_ZCHUNKS (WB_HALFS / 8)        // 147456 uint4 chunks
#define WB_ZBLOCKS (WB_ZCHUNKS / 2 / 256) // 288 zero-blocks per conv half

__device__ __align__(16) __half g_Wb[WB_HALFS];                 // fp16 padded B blocks
__device__ __align__(16) __half g_Xh[(size_t)MAXROWS * INDIM];  // fp16 x, zero-padded
__device__ int    g_is64;

// ============================================================
// Helpers
// ============================================================
__device__ __forceinline__ uint32_t smem_u32(const void* p) {
    uint32_t a;
    asm("{ .reg .u64 t; cvta.to.shared.u64 t, %1; cvt.u32.u64 %0, t; }" : "=r"(a) : "l"(p));
    return a;
}
__device__ __forceinline__ void cp_async16(uint32_t dst, const void* src) {
    asm volatile("cp.async.cg.shared.global [%0], [%1], 16;" :: "r"(dst), "l"(src));
}
#define CP_COMMIT() asm volatile("cp.async.commit_group;" ::: "memory")
#define CP_WAIT0()  asm volatile("cp.async.wait_group 0;" ::: "memory")
#define CP_WAIT1()  asm volatile("cp.async.wait_group 1;" ::: "memory")

__device__ __forceinline__ void ldsm4(uint32_t& r0, uint32_t& r1, uint32_t& r2,
                                      uint32_t& r3, uint32_t addr) {
    asm volatile("ldmatrix.sync.aligned.m8n8.x4.shared.b16 {%0,%1,%2,%3}, [%4];"
        : "=r"(r0), "=r"(r1), "=r"(r2), "=r"(r3) : "r"(addr));
}
__device__ __forceinline__ void mma_fp16(float* d, const uint32_t* a, const uint32_t* b) {
    asm volatile(
        "mma.sync.aligned.m16n8k16.row.col.f32.f16.f16.f32 "
        "{%0,%1,%2,%3}, {%4,%5,%6,%7}, {%8,%9}, {%0,%1,%2,%3};"
        : "+f"(d[0]), "+f"(d[1]), "+f"(d[2]), "+f"(d[3])
        : "r"(a[0]), "r"(a[1]), "r"(a[2]), "r"(a[3]), "r"(b[0]), "r"(b[1]));
}

// ============================================================
// conv body: convert one half of x rows to fp16, zero part of g_Wb
// ============================================================
__device__ __forceinline__ void conv_body(const float* __restrict__ x,
                                          int row_base, int n_tok, int zofs) {
    int i = blockIdx.x * 256 + threadIdx.x;          // chunk: 8 halfs
    int row = row_base + (i >> 7);
    int c   = i & 127;
    __half2 h[4];
    if (row < n_tok) {
        const float4* src = reinterpret_cast<const float4*>(x + (size_t)row * INDIM + c * 8);
        float4 v0 = src[0], v1 = src[1];
        h[0] = __floats2half2_rn(v0.x, v0.y);
        h[1] = __floats2half2_rn(v0.z, v0.w);
        h[2] = __floats2half2_rn(v1.x, v1.y);
        h[3] = __floats2half2_rn(v1.z, v1.w);
    } else {
        h[0] = h[1] = h[2] = h[3] = __floats2half2_rn(0.f, 0.f);
    }
    *reinterpret_cast<uint4*>(g_Xh + ((size_t)row * 128 + c) * 8) = *reinterpret_cast<uint4*>(h);

    if (blockIdx.x < WB_ZBLOCKS) {
        int zi = zofs + blockIdx.x * 256 + threadIdx.x;
        uint4 z = make_uint4(0, 0, 0, 0);
        reinterpret_cast<uint4*>(g_Wb)[zi] = z;
    }
}

__global__ void conv0_kernel(const float* __restrict__ x, const int* __restrict__ ei,
                             int n_tok) {
    conv_body(x, 0, n_tok, 0);
    if (blockIdx.x == 0) {
        __shared__ int allzero;
        if (threadIdx.x == 0) allzero = 1;
        __syncthreads();
        if (ei[threadIdx.x * 2 + 1] != 0) allzero = 0;
        __syncthreads();
        if (threadIdx.x == 0) g_is64 = allzero;
    }
}

__global__ void conv1_kernel(const float* __restrict__ x, int n_tok) {
    conv_body(x, HALFROWS, n_tok, WB_ZCHUNKS / 2);
}

// ============================================================
// scatter: atomicAdd fp16 directly into the padded block layout.
// Entry (r, c): block = (r>>7)*KTILES + (c>>6), row r&127, col c&63.
// ============================================================
__global__ void scatter_kernel(const int* __restrict__ ei,
                               const float* __restrict__ val, int nnz) {
    int i = blockIdx.x * 256 + threadIdx.x;
    if (i >= nnz) return;
    int r, c;
    if (g_is64) {
        const long long* e = (const long long*)ei;
        r = (int)e[i];
        c = (int)e[nnz + i];
    } else {
        r = ei[i];
        c = ei[nnz + i];
    }
    int blk = (r >> 7) * KTILES + (c >> 6);
    size_t off = (size_t)blk * (BN * (ROWB / 2)) + (r & 127) * (ROWB / 2) + (c & 63);
    atomicAdd(&g_Wb[off], __float2half(val[i]));
}

// ============================================================
// GEMM: out[m,n] = sum_k X[m,k]*W[n,k] + bias[n]   (identical to R11)
// ============================================================
__global__ void __launch_bounds__(THREADS, 2)
gemm_kernel(const float* __restrict__ bias, float* __restrict__ out, int n_tok) {
    extern __shared__ char smem[];
    uint32_t sbase = smem_u32(smem);

    const int tid  = threadIdx.x;
    const int wid  = tid >> 5;
    const int lane = tid & 31;
    const int g    = lane >> 2;
    const int t    = lane & 3;

    const int n0 = (blockIdx.x & 7) * BN;   // n fastest -> A-tile L2 reuse
    const int m0 = (blockIdx.x >> 3) * BM;
    const int nt = n0 >> 7;

    const int wm = (wid & 1) * 64;
    const int wn = (wid >> 1) * 32;

    // ldmatrix per-lane offsets (within a stage)
    const uint32_t a_lane = (uint32_t)(wm + (lane & 15)) * ROWB + (lane >> 4) * 16;
    const uint32_t b_lane = (uint32_t)(wn + (lane >> 4) * 8 + (lane & 7)) * ROWB
                            + ((lane >> 3) & 1) * 16 + A_BYTES;

    // ---- stage loader: A 1024 chunks + B 1152 chunks of 16B ----
    auto load_stage = [&](uint32_t dst, int kc) {
        #pragma unroll
        for (int it = 0; it < 4; it++) {
            int ch = tid + it * THREADS;
            int r = ch >> 3, c = ch & 7;
            cp_async16(dst + r * ROWB + c * 16,
                       g_Xh + (size_t)(m0 + r) * INDIM + kc * 64 + c * 8);
        }
        const char* bsrc = reinterpret_cast<const char*>(g_Wb)
                           + ((size_t)nt * KTILES + kc) * B_BYTES;
        uint32_t dstB = dst + A_BYTES;
        #pragma unroll
        for (int it = 0; it < 5; it++) {
            int ch = tid + it * THREADS;
            if (ch < 1152) cp_async16(dstB + ch * 16, bsrc + ch * 16);
        }
        CP_COMMIT();
    };

    float acc[4][4][4];
    #pragma unroll
    for (int i = 0; i < 4; i++)
        #pragma unroll
        for (int j = 0; j < 4; j++)
            #pragma unroll
            for (int r = 0; r < 4; r++) acc[i][j][r] = 0.f;

    uint32_t afrag[2][4][4];
    uint32_t bfrag[2][4][2];

    uint32_t st0 = sbase;                     // stage holding kc
    uint32_t st1 = sbase + STAGE_BYTES;       // kc+1
    uint32_t st2 = sbase + 2 * STAGE_BYTES;   // kc+2 (being filled)

    load_stage(st0, 0);
    load_stage(st1, 1);

    for (int kc = 0; kc < KTILES; kc++) {
        if (kc + 1 < KTILES) { CP_WAIT1(); } else { CP_WAIT0(); }
        __syncthreads();                      // stage st0 (kc) ready for all warps
        if (kc + 2 < KTILES) load_stage(st2, kc + 2);

        const uint32_t aaddr = st0 + a_lane;
        const uint32_t baddr = st0 + b_lane;

        // fragment loader for one k16 slice into buffer fb
        auto load_frag = [&](int ks, int fb) {
            #pragma unroll
            for (int tm = 0; tm < 4; tm++)
                ldsm4(afrag[fb][tm][0], afrag[fb][tm][1],
                      afrag[fb][tm][2], afrag[fb][tm][3],
                      aaddr + tm * (16 * ROWB) + ks * 32);
            #pragma unroll
            for (int tnp = 0; tnp < 2; tnp++) {
                uint32_t r0, r1, r2, r3;
                ldsm4(r0, r1, r2, r3, baddr + tnp * (16 * ROWB) + ks * 32);
                bfrag[fb][2 * tnp][0]     = r0;
                bfrag[fb][2 * tnp][1]     = r1;
                bfrag[fb][2 * tnp + 1][0] = r2;
                bfrag[fb][2 * tnp + 1][1] = r3;
            }
        };

        load_frag(0, 0);
        #pragma unroll
        for (int ks = 0; ks < 4; ks++) {
            const int cur = ks & 1;
            if (ks < 3) load_frag(ks + 1, cur ^ 1);   // hide LDSM under MMAs
            #pragma unroll
            for (int tm = 0; tm < 4; tm++)
                #pragma unroll
                for (int tn = 0; tn < 4; tn++)
                    mma_fp16(acc[tm][tn], afrag[cur][tm], bfrag[cur][tn]);
        }

        // rotate stage bases (3 registers, no modulo)
        uint32_t tmp = st0; st0 = st1; st1 = st2; st2 = tmp;
    }

    // ---- epilogue: add bias, store (float2 per row-piece) ----
    #pragma unroll
    for (int tn = 0; tn < 4; tn++) {
        const int c = n0 + wn + tn * 8 + 2 * t;
        const float bv0 = bias[c];
        const float bv1 = bias[c + 1];
        #pragma unroll
        for (int tm = 0; tm < 4; tm++) {
            const int r0 = m0 + wm + tm * 16 + g;
            const int r1 = r0 + 8;
            if (r0 < n_tok) {
                float2 v = make_float2(acc[tm][tn][0] + bv0, acc[tm][tn][1] + bv1);
                *reinterpret_cast<float2*>(&out[(size_t)r0 * OUTDIM + c]) = v;
            }
            if (r1 < n_tok) {
                float2 v = make_float2(acc[tm][tn][2] + bv0, acc[tm][tn][3] + bv1);
                *reinterpret_cast<float2*>(&out[(size_t)r1 * OUTDIM + c]) = v;
            }
        }
    }
}

// ============================================================
// Launch: 4 kernels (conv0, conv1, scatter, gemm) -> gemm is #4
// ============================================================
extern "C" void kernel_launch(void* const* d_in, const int* in_sizes, int n_in,
                              void* d_out, int out_size) {
    const float* x    = (const float*)d_in[0];
    const float* wval = (const float*)d_in[1];
    const float* bias = (const float*)d_in[2];
    const int*   ei   = (const int*)d_in[3];

    int n_tok = in_sizes[0] / INDIM;           // 50000
    int nnz   = in_sizes[1];                   // 65536
    float* out = (float*)d_out;

    conv0_kernel<<<(HALFROWS * (INDIM / 8)) / 256, 256>>>(x, ei, n_tok);
    conv1_kernel<<<(HALFROWS * (INDIM / 8)) / 256, 256>>>(x, n_tok);
    scatter_kernel<<<(nnz + 255) / 256, 256>>>(ei, wval, nnz);

    int mtiles = (n_tok + BM - 1) / BM;        // 391
    cudaFuncSetAttribute(gemm_kernel, cudaFuncAttributeMaxDynamicSharedMemorySize, SMEM_BYTES);
    gemm_kernel<<<mtiles * (OUTDIM / BN), THREADS, SMEM_BYTES>>>(bias, out, n_tok);
}